// round 3
// baseline (speedup 1.0000x reference)
#include <cuda_runtime.h>

// HaversineSmoothedLoss — single fused kernel.
//   a  = (1 - u1·u2)/2            (unit 3-vectors; no per-pair trig)
//   w  = exp2( sqrt(a) * Q(a) )   Q = K*log2(e) * asin-series; far cells skipped by warp vote
//   loss_b = log(Z_b) - (Σ w·x)/S_b ,  Z = Σ e^x, S = Σ w
//
// Grid: 2048 blocks = 128 row-groups (4 rows) × 16 cell-chunks (2048 cells).
// Phase A: block computes its chunk's cell unit vectors into SMEM (24 KB).
// Phase B: fused pass; logits via float4 LDG, celltab via LDS.128.
// Phase C: partials to gmem; the LAST block (arrival counter) reduces all
//          partials to the scalar loss and resets the counter (deterministic:
//          one block, fixed read order).

#define C_CELLS 32768
#define B_ROWS  512
#define RPB     4
#define SPLIT   16
#define CHUNK   (C_CELLS / SPLIT)    // 2048
#define THREADS 256
#define GRID    ((B_ROWS / RPB) * SPLIT)  // 2048

__device__ float d_pZ[B_ROWS * SPLIT];
__device__ float d_pS[B_ROWS * SPLIT];
__device__ float d_pW[B_ROWS * SPLIT];
__device__ unsigned int d_ctr = 0;

__device__ __forceinline__ float fsqrt_ap(float a) {
    float r; asm("sqrt.approx.f32 %0, %1;" : "=f"(r) : "f"(a)); return r;
}
__device__ __forceinline__ float fexp2_ap(float a) {
    float r; asm("ex2.approx.f32 %0, %1;" : "=f"(r) : "f"(a)); return r;
}

__global__ __launch_bounds__(THREADS)
void fused_kernel(const float* __restrict__ logits,
                  const float* __restrict__ latlon,
                  const float* __restrict__ geo,
                  float* __restrict__ out) {
    const int bx    = blockIdx.x;
    const int rg    = bx >> 4;            // row group 0..127
    const int ch    = bx & (SPLIT - 1);   // chunk 0..15
    const int row0  = rg * RPB;
    const int tid   = threadIdx.x;
    const int cell0 = ch * CHUNK;

    __shared__ float s_ux[CHUNK];
    __shared__ float s_uy[CHUNK];
    __shared__ float s_uz[CHUNK];

    const float d2r   = 0.017453292519943295f;
    const float LOG2E = 1.4426950408889634f;
    const float KL  = -245.104328f;   // -(2*6371/75)*log2(e)
    const float KL3 = -40.8507213f;   // KL/6
    const float KL5 = -18.3828246f;   // KL*3/40
    const float KL7 = -10.9421575f;   // KL*15/336
    const float ATH = 0.03f;          // w < 1.4e-13 beyond this

    // ---- Phase A: cell unit vectors for this chunk into SMEM ----
    #pragma unroll
    for (int i = tid; i < CHUNK; i += THREADS) {
        const int c = cell0 + i;
        float lat = geo[2 * c]     * d2r;
        float lon = geo[2 * c + 1] * d2r;
        float sl, cl, so, co;
        sincosf(lat, &sl, &cl);
        sincosf(lon, &so, &co);
        s_ux[i] = sl;
        s_uy[i] = cl * so;
        s_uz[i] = cl * co;
    }

    // Row unit vectors (scaled by -1/2), registers.
    float nx[RPB], ny[RPB], nz[RPB];
    #pragma unroll
    for (int r = 0; r < RPB; r++) {
        float lat = latlon[2 * (row0 + r)]     * d2r;
        float lon = latlon[2 * (row0 + r) + 1] * d2r;
        float sl, cl, so, co;
        sincosf(lat, &sl, &cl);
        sincosf(lon, &so, &co);
        nx[r] = -0.5f * sl;
        ny[r] = -0.5f * cl * so;
        nz[r] = -0.5f * cl * co;
    }
    __syncthreads();

    // ---- Phase B: fused pass ----
    float Z[RPB], S[RPB], WX[RPB];
    #pragma unroll
    for (int r = 0; r < RPB; r++) { Z[r] = 0.f; S[r] = 0.f; WX[r] = 0.f; }

    const float4* sx4 = (const float4*)s_ux;
    const float4* sy4 = (const float4*)s_uy;
    const float4* sz4 = (const float4*)s_uz;

    #pragma unroll
    for (int it = 0; it < CHUNK / (THREADS * 4); it++) {   // 2 iterations
        const int v  = it * THREADS + tid;                 // float4 idx in chunk
        const float4 gx = sx4[v];
        const float4 gy = sy4[v];
        const float4 gz = sz4[v];

        #pragma unroll
        for (int r = 0; r < RPB; r++) {
            const size_t gbase = ((size_t)(row0 + r) * C_CELLS + cell0) >> 2;
            const float4 x4 = __ldg((const float4*)logits + gbase + v);
            const float xs[4]  = {x4.x, x4.y, x4.z, x4.w};
            const float gxs[4] = {gx.x, gx.y, gx.z, gx.w};
            const float gys[4] = {gy.x, gy.y, gy.z, gy.w};
            const float gzs[4] = {gz.x, gz.y, gz.z, gz.w};
            #pragma unroll
            for (int k = 0; k < 4; k++) {
                const float x = xs[k];
                Z[r] += fexp2_ap(x * LOG2E);
                float a = fmaf(nx[r], gxs[k],
                          fmaf(ny[r], gys[k],
                          fmaf(nz[r], gzs[k], 0.5f)));
                if (__any_sync(0xffffffffu, a < ATH)) {
                    a = fmaxf(a, 1e-18f);
                    float s = fsqrt_ap(a);
                    float q = fmaf(a, fmaf(a, fmaf(a, KL7, KL5), KL3), KL);
                    float w = fexp2_ap(s * q);
                    S[r]  += w;
                    WX[r]  = fmaf(w, x, WX[r]);
                }
            }
        }
    }

    // ---- Block reduction of 12 accumulators (deterministic tree) ----
    float acc[12];
    #pragma unroll
    for (int r = 0; r < RPB; r++) {
        acc[r * 3 + 0] = Z[r]; acc[r * 3 + 1] = S[r]; acc[r * 3 + 2] = WX[r];
    }
    __shared__ float red[12][THREADS / 32];
    const int lane = tid & 31, warp = tid >> 5;
    #pragma unroll
    for (int i = 0; i < 12; i++) {
        float vv = acc[i];
        #pragma unroll
        for (int o = 16; o > 0; o >>= 1) vv += __shfl_down_sync(0xffffffffu, vv, o);
        if (lane == 0) red[i][warp] = vv;
    }
    __syncthreads();
    if (tid < 12) {
        float vv = 0.f;
        #pragma unroll
        for (int wi = 0; wi < THREADS / 32; wi++) vv += red[tid][wi];
        const int r     = tid / 3;
        const int which = tid % 3;
        const int idx   = (row0 + r) * SPLIT + ch;
        if      (which == 0) d_pZ[idx] = vv;
        else if (which == 1) d_pS[idx] = vv;
        else                 d_pW[idx] = vv;
    }

    // ---- Phase C: last block reduces everything ----
    __shared__ bool isLast;
    __syncthreads();                     // partial writes done block-wide
    if (tid == 0) {
        __threadfence();                 // make partials visible before arrival
        unsigned int t = atomicAdd(&d_ctr, 1u);
        isLast = (t == (unsigned int)(GRID - 1));
    }
    __syncthreads();

    if (isLast) {
        // 256 threads, each handles rows tid and tid+256.
        float v = 0.f;
        #pragma unroll
        for (int half = 0; half < 2; half++) {
            const int b = tid + half * THREADS;
            float Zt = 0.f, St = 0.f, Wt = 0.f;
            #pragma unroll
            for (int cc = 0; cc < SPLIT; cc++) {
                Zt += __ldcg(&d_pZ[b * SPLIT + cc]);
                St += __ldcg(&d_pS[b * SPLIT + cc]);
                Wt += __ldcg(&d_pW[b * SPLIT + cc]);
            }
            v += logf(Zt) - Wt * __fdividef(1.0f, St);
        }
        __shared__ float fin[THREADS / 32];
        #pragma unroll
        for (int o = 16; o > 0; o >>= 1) v += __shfl_down_sync(0xffffffffu, v, o);
        if (lane == 0) fin[warp] = v;
        __syncthreads();
        if (tid == 0) {
            float s = 0.f;
            #pragma unroll
            for (int i = 0; i < THREADS / 32; i++) s += fin[i];
            out[0] = s * (1.0f / (float)B_ROWS);
            d_ctr  = 0;                  // reset for next graph replay
        }
    }
}

extern "C" void kernel_launch(void* const* d_in, const int* in_sizes, int n_in,
                              void* d_out, int out_size) {
    const float* logits = (const float*)d_in[0];   // [512, 32768]
    const float* latlon = (const float*)d_in[1];   // [512, 2]
    const float* geo    = (const float*)d_in[2];   // [32768, 2]

    fused_kernel<<<GRID, THREADS>>>(logits, latlon, geo, (float*)d_out);
}

// round 4
// speedup vs baseline: 1.0463x; 1.0463x over previous
#include <cuda_runtime.h>

// HaversineSmoothedLoss — single fused kernel, v2.
//   a  = (1 - u1·u2)/2            (unit 3-vectors; no per-pair trig)
//   w  = exp2( sqrt(a) * Q(a) )   Q = K*log2(e) * asin-series; far cells skipped by warp vote
//   loss_b = log(Z_b) - (Σ w·x)/S_b ,  Z = Σ e^x, S = Σ w
//
// Grid: 1024 blocks = 64 row-groups (8 rows) × 16 cell-chunks (2048 cells).
// Phase A: block builds its chunk's cell unit vectors in SMEM with __sincosf
//          (approx — 2 MUFU per call, ~10x cheaper than round-3's sincosf).
// Phase B: fused pass; 8 logits LDG.128 front-batched per iter, celltab via LDS.128.
// Phase C: last block (arrival counter) reduces partials, writes loss, resets counter.

#define C_CELLS 32768
#define B_ROWS  512
#define RPB     8
#define SPLIT   16
#define CHUNK   (C_CELLS / SPLIT)          // 2048
#define THREADS 256
#define GRID    ((B_ROWS / RPB) * SPLIT)   // 1024

__device__ float d_pZ[B_ROWS * SPLIT];
__device__ float d_pS[B_ROWS * SPLIT];
__device__ float d_pW[B_ROWS * SPLIT];
__device__ unsigned int d_ctr = 0;

__device__ __forceinline__ float fsqrt_ap(float a) {
    float r; asm("sqrt.approx.f32 %0, %1;" : "=f"(r) : "f"(a)); return r;
}
__device__ __forceinline__ float fexp2_ap(float a) {
    float r; asm("ex2.approx.f32 %0, %1;" : "=f"(r) : "f"(a)); return r;
}

__global__ __launch_bounds__(THREADS)
void fused_kernel(const float* __restrict__ logits,
                  const float* __restrict__ latlon,
                  const float* __restrict__ geo,
                  float* __restrict__ out) {
    const int bx    = blockIdx.x;
    const int rg    = bx >> 4;             // row group 0..63
    const int ch    = bx & (SPLIT - 1);    // chunk 0..15
    const int row0  = rg * RPB;
    const int tid   = threadIdx.x;
    const int cell0 = ch * CHUNK;

    __shared__ float s_ux[CHUNK];
    __shared__ float s_uy[CHUNK];
    __shared__ float s_uz[CHUNK];
    __shared__ float s_row[3][RPB];        // -0.5 * row unit vectors

    const float d2r   = 0.017453292519943295f;
    const float LOG2E = 1.4426950408889634f;
    const float KL  = -245.104328f;        // -(2*6371/75)*log2(e)
    const float KL3 = -40.8507213f;        // KL/6
    const float KL5 = -18.3828246f;        // KL*3/40
    const float KL7 = -10.9421575f;        // KL*15/336
    const float ATH = 0.03f;               // w < 1.4e-13 beyond this

    // ---- Phase A: cell unit vectors (approx sincos) ----
    const float2* __restrict__ geo2 = (const float2*)geo;
    #pragma unroll
    for (int i = tid; i < CHUNK; i += THREADS) {
        float2 ll = __ldg(geo2 + cell0 + i);
        float sl, cl, so, co;
        __sincosf(ll.x * d2r, &sl, &cl);
        __sincosf(ll.y * d2r, &so, &co);
        s_ux[i] = sl;
        s_uy[i] = cl * so;
        s_uz[i] = cl * co;
    }
    // Row unit vectors: 8 threads, precise sincosf (only 16 calls per block).
    if (tid < RPB) {
        float lat = latlon[2 * (row0 + tid)]     * d2r;
        float lon = latlon[2 * (row0 + tid) + 1] * d2r;
        float sl, cl, so, co;
        sincosf(lat, &sl, &cl);
        sincosf(lon, &so, &co);
        s_row[0][tid] = -0.5f * sl;
        s_row[1][tid] = -0.5f * cl * so;
        s_row[2][tid] = -0.5f * cl * co;
    }
    __syncthreads();

    float nx[RPB], ny[RPB], nz[RPB];
    #pragma unroll
    for (int r = 0; r < RPB; r++) {
        nx[r] = s_row[0][r]; ny[r] = s_row[1][r]; nz[r] = s_row[2][r];
    }

    // ---- Phase B: fused pass ----
    float Z[RPB], S[RPB], WX[RPB];
    #pragma unroll
    for (int r = 0; r < RPB; r++) { Z[r] = 0.f; S[r] = 0.f; WX[r] = 0.f; }

    const float4* sx4 = (const float4*)s_ux;
    const float4* sy4 = (const float4*)s_uy;
    const float4* sz4 = (const float4*)s_uz;
    const float4* __restrict__ lg4 = (const float4*)logits;

    int rowbase[RPB];
    #pragma unroll
    for (int r = 0; r < RPB; r++)
        rowbase[r] = ((row0 + r) * C_CELLS + cell0) >> 2;

    #pragma unroll
    for (int it = 0; it < CHUNK / (THREADS * 4); it++) {   // 2 iterations
        const int v = it * THREADS + tid;

        // Front-batch the 8 global loads (MLP).
        float4 xr[RPB];
        #pragma unroll
        for (int r = 0; r < RPB; r++)
            xr[r] = __ldg(lg4 + rowbase[r] + v);

        const float4 gx = sx4[v];
        const float4 gy = sy4[v];
        const float4 gz = sz4[v];
        const float gxs[4] = {gx.x, gx.y, gx.z, gx.w};
        const float gys[4] = {gy.x, gy.y, gy.z, gy.w};
        const float gzs[4] = {gz.x, gz.y, gz.z, gz.w};

        #pragma unroll
        for (int r = 0; r < RPB; r++) {
            const float xs[4] = {xr[r].x, xr[r].y, xr[r].z, xr[r].w};
            #pragma unroll
            for (int k = 0; k < 4; k++) {
                const float x = xs[k];
                Z[r] += fexp2_ap(x * LOG2E);
                float a = fmaf(nx[r], gxs[k],
                          fmaf(ny[r], gys[k],
                          fmaf(nz[r], gzs[k], 0.5f)));
                if (__any_sync(0xffffffffu, a < ATH)) {
                    a = fmaxf(a, 1e-18f);
                    float s = fsqrt_ap(a);
                    float q = fmaf(a, fmaf(a, fmaf(a, KL7, KL5), KL3), KL);
                    float w = fexp2_ap(s * q);
                    S[r]  += w;
                    WX[r]  = fmaf(w, x, WX[r]);
                }
            }
        }
    }

    // ---- Block reduction of 24 accumulators (deterministic tree) ----
    float acc[3 * RPB];
    #pragma unroll
    for (int r = 0; r < RPB; r++) {
        acc[r * 3 + 0] = Z[r]; acc[r * 3 + 1] = S[r]; acc[r * 3 + 2] = WX[r];
    }
    __shared__ float red[3 * RPB][THREADS / 32];
    const int lane = tid & 31, warp = tid >> 5;
    #pragma unroll
    for (int i = 0; i < 3 * RPB; i++) {
        float vv = acc[i];
        #pragma unroll
        for (int o = 16; o > 0; o >>= 1) vv += __shfl_down_sync(0xffffffffu, vv, o);
        if (lane == 0) red[i][warp] = vv;
    }
    __syncthreads();
    if (tid < 3 * RPB) {
        float vv = 0.f;
        #pragma unroll
        for (int wi = 0; wi < THREADS / 32; wi++) vv += red[tid][wi];
        const int r     = tid / 3;
        const int which = tid % 3;
        const int idx   = (row0 + r) * SPLIT + ch;
        if      (which == 0) d_pZ[idx] = vv;
        else if (which == 1) d_pS[idx] = vv;
        else                 d_pW[idx] = vv;
    }

    // ---- Phase C: last block reduces everything ----
    __shared__ bool isLast;
    __syncthreads();
    if (tid == 0) {
        __threadfence();
        unsigned int t = atomicAdd(&d_ctr, 1u);
        isLast = (t == (unsigned int)(GRID - 1));
    }
    __syncthreads();

    if (isLast) {
        float v = 0.f;
        #pragma unroll
        for (int half = 0; half < B_ROWS / THREADS; half++) {   // 2 rows/thread
            const int b = tid + half * THREADS;
            float Zt = 0.f, St = 0.f, Wt = 0.f;
            #pragma unroll
            for (int cc = 0; cc < SPLIT; cc++) {
                Zt += __ldcg(&d_pZ[b * SPLIT + cc]);
                St += __ldcg(&d_pS[b * SPLIT + cc]);
                Wt += __ldcg(&d_pW[b * SPLIT + cc]);
            }
            v += logf(Zt) - Wt * __fdividef(1.0f, St);
        }
        __shared__ float fin[THREADS / 32];
        #pragma unroll
        for (int o = 16; o > 0; o >>= 1) v += __shfl_down_sync(0xffffffffu, v, o);
        if (lane == 0) fin[warp] = v;
        __syncthreads();
        if (tid == 0) {
            float s = 0.f;
            #pragma unroll
            for (int i = 0; i < THREADS / 32; i++) s += fin[i];
            out[0] = s * (1.0f / (float)B_ROWS);
            d_ctr  = 0;   // reset for graph replay
        }
    }
}

extern "C" void kernel_launch(void* const* d_in, const int* in_sizes, int n_in,
                              void* d_out, int out_size) {
    const float* logits = (const float*)d_in[0];   // [512, 32768]
    const float* latlon = (const float*)d_in[1];   // [512, 2]
    const float* geo    = (const float*)d_in[2];   // [32768, 2]

    fused_kernel<<<GRID, THREADS>>>(logits, latlon, geo, (float*)d_out);
}

// round 5
// speedup vs baseline: 1.0921x; 1.0437x over previous
#include <cuda_runtime.h>

// HaversineSmoothedLoss — single fused kernel, v3 (occupancy fix).
//   a  = (1 - u1·u2)/2            (unit 3-vectors; no per-pair trig)
//   w  = exp2( sqrt(a) * Q(a) )   Q = K*log2(e) * asin-series; far cells skipped by warp vote
//   loss_b = log(Z_b) - (Σ w·x)/S_b ,  Z = Σ e^x, S = Σ w
//
// Grid: 2048 blocks (512 thr) = 128 row-groups (4 rows) × 16 cell-chunks (2048 cells).
// One float4 cell-quad per thread -> minimal register state, high occupancy.
// Phase A: chunk cell unit vectors in SMEM via __sincosf (approx, cheap).
// Phase C: last block (arrival counter) reduces partials, writes loss, resets counter.

#define C_CELLS 32768
#define B_ROWS  512
#define RPB     4
#define SPLIT   16
#define CHUNK   (C_CELLS / SPLIT)          // 2048
#define THREADS 512
#define NWARPS  (THREADS / 32)             // 16
#define GRID    ((B_ROWS / RPB) * SPLIT)   // 2048

__device__ float d_pZ[B_ROWS * SPLIT];
__device__ float d_pS[B_ROWS * SPLIT];
__device__ float d_pW[B_ROWS * SPLIT];
__device__ unsigned int d_ctr = 0;

__device__ __forceinline__ float fsqrt_ap(float a) {
    float r; asm("sqrt.approx.f32 %0, %1;" : "=f"(r) : "f"(a)); return r;
}
__device__ __forceinline__ float fexp2_ap(float a) {
    float r; asm("ex2.approx.f32 %0, %1;" : "=f"(r) : "f"(a)); return r;
}

__global__ __launch_bounds__(THREADS, 2)
void fused_kernel(const float* __restrict__ logits,
                  const float* __restrict__ latlon,
                  const float* __restrict__ geo,
                  float* __restrict__ out) {
    const int bx    = blockIdx.x;
    const int rg    = bx >> 4;             // row group 0..127
    const int ch    = bx & (SPLIT - 1);    // chunk 0..15
    const int row0  = rg * RPB;
    const int tid   = threadIdx.x;
    const int cell0 = ch * CHUNK;

    __shared__ float s_ux[CHUNK];
    __shared__ float s_uy[CHUNK];
    __shared__ float s_uz[CHUNK];
    __shared__ float s_row[3][RPB];        // -0.5 * row unit vectors

    const float d2r   = 0.017453292519943295f;
    const float LOG2E = 1.4426950408889634f;
    const float KL  = -245.104328f;        // -(2*6371/75)*log2(e)
    const float KL3 = -40.8507213f;        // KL/6
    const float KL5 = -18.3828246f;        // KL*3/40
    const float KL7 = -10.9421575f;        // KL*15/336
    const float ATH = 0.03f;               // w < 1.4e-13 beyond this

    // ---- Phase A: cell unit vectors (approx sincos), 4 cells/thread ----
    const float2* __restrict__ geo2 = (const float2*)geo;
    #pragma unroll
    for (int i = tid; i < CHUNK; i += THREADS) {
        float2 ll = __ldg(geo2 + cell0 + i);
        float sl, cl, so, co;
        __sincosf(ll.x * d2r, &sl, &cl);
        __sincosf(ll.y * d2r, &so, &co);
        s_ux[i] = sl;
        s_uy[i] = cl * so;
        s_uz[i] = cl * co;
    }
    if (tid < RPB) {   // row unit vectors: 4 precise sincos pairs per block
        float lat = latlon[2 * (row0 + tid)]     * d2r;
        float lon = latlon[2 * (row0 + tid) + 1] * d2r;
        float sl, cl, so, co;
        sincosf(lat, &sl, &cl);
        sincosf(lon, &so, &co);
        s_row[0][tid] = -0.5f * sl;
        s_row[1][tid] = -0.5f * cl * so;
        s_row[2][tid] = -0.5f * cl * co;
    }
    __syncthreads();

    // ---- Phase B: one float4 quad per thread, 4 rows ----
    const float4* __restrict__ lg4 = (const float4*)logits;
    const int v = tid;                                   // quad index in chunk
    const int qbase = (cell0 >> 2) + v;

    float4 xr[RPB];                                      // front-batched LDG.128 x4
    #pragma unroll
    for (int r = 0; r < RPB; r++)
        xr[r] = __ldg(lg4 + (size_t)(row0 + r) * (C_CELLS / 4) + qbase);

    const float4 gx = ((const float4*)s_ux)[v];
    const float4 gy = ((const float4*)s_uy)[v];
    const float4 gz = ((const float4*)s_uz)[v];
    const float gxs[4] = {gx.x, gx.y, gx.z, gx.w};
    const float gys[4] = {gy.x, gy.y, gy.z, gy.w};
    const float gzs[4] = {gz.x, gz.y, gz.z, gz.w};

    float Z[RPB], S[RPB], WX[RPB];
    #pragma unroll
    for (int r = 0; r < RPB; r++) { Z[r] = 0.f; S[r] = 0.f; WX[r] = 0.f; }

    #pragma unroll
    for (int r = 0; r < RPB; r++) {
        const float nxr = s_row[0][r], nyr = s_row[1][r], nzr = s_row[2][r];
        const float xs[4] = {xr[r].x, xr[r].y, xr[r].z, xr[r].w};
        #pragma unroll
        for (int k = 0; k < 4; k++) {
            const float x = xs[k];
            Z[r] += fexp2_ap(x * LOG2E);
            float a = fmaf(nxr, gxs[k], fmaf(nyr, gys[k], fmaf(nzr, gzs[k], 0.5f)));
            if (__any_sync(0xffffffffu, a < ATH)) {
                a = fmaxf(a, 1e-18f);
                float s = fsqrt_ap(a);
                float q = fmaf(a, fmaf(a, fmaf(a, KL7, KL5), KL3), KL);
                float w = fexp2_ap(s * q);
                S[r]  += w;
                WX[r]  = fmaf(w, x, WX[r]);
            }
        }
    }

    // ---- Block reduction of 12 accumulators (deterministic tree) ----
    float acc[3 * RPB];
    #pragma unroll
    for (int r = 0; r < RPB; r++) {
        acc[r * 3 + 0] = Z[r]; acc[r * 3 + 1] = S[r]; acc[r * 3 + 2] = WX[r];
    }
    __shared__ float red[3 * RPB][NWARPS];
    const int lane = tid & 31, warp = tid >> 5;
    #pragma unroll
    for (int i = 0; i < 3 * RPB; i++) {
        float vv = acc[i];
        #pragma unroll
        for (int o = 16; o > 0; o >>= 1) vv += __shfl_down_sync(0xffffffffu, vv, o);
        if (lane == 0) red[i][warp] = vv;
    }
    __syncthreads();
    if (tid < 3 * RPB) {
        float vv = 0.f;
        #pragma unroll
        for (int wi = 0; wi < NWARPS; wi++) vv += red[tid][wi];
        const int r     = tid / 3;
        const int which = tid % 3;
        const int idx   = (row0 + r) * SPLIT + ch;
        if      (which == 0) d_pZ[idx] = vv;
        else if (which == 1) d_pS[idx] = vv;
        else                 d_pW[idx] = vv;
    }

    // ---- Phase C: last block reduces everything ----
    __shared__ bool isLast;
    __syncthreads();
    if (tid == 0) {
        __threadfence();
        unsigned int t = atomicAdd(&d_ctr, 1u);
        isLast = (t == (unsigned int)(GRID - 1));
    }
    __syncthreads();

    if (isLast) {
        // 512 threads: one row each.
        const int b = tid;
        float Zt = 0.f, St = 0.f, Wt = 0.f;
        #pragma unroll
        for (int cc = 0; cc < SPLIT; cc++) {
            Zt += __ldcg(&d_pZ[b * SPLIT + cc]);
            St += __ldcg(&d_pS[b * SPLIT + cc]);
            Wt += __ldcg(&d_pW[b * SPLIT + cc]);
        }
        float vv = logf(Zt) - Wt * __fdividef(1.0f, St);

        __shared__ float fin[NWARPS];
        #pragma unroll
        for (int o = 16; o > 0; o >>= 1) vv += __shfl_down_sync(0xffffffffu, vv, o);
        if (lane == 0) fin[warp] = vv;
        __syncthreads();
        if (tid == 0) {
            float s = 0.f;
            #pragma unroll
            for (int i = 0; i < NWARPS; i++) s += fin[i];
            out[0] = s * (1.0f / (float)B_ROWS);
            d_ctr  = 0;   // reset for graph replay
        }
    }
}

extern "C" void kernel_launch(void* const* d_in, const int* in_sizes, int n_in,
                              void* d_out, int out_size) {
    const float* logits = (const float*)d_in[0];   // [512, 32768]
    const float* latlon = (const float*)d_in[1];   // [512, 2]
    const float* geo    = (const float*)d_in[2];   // [32768, 2]

    fused_kernel<<<GRID, THREADS>>>(logits, latlon, geo, (float*)d_out);
}

// round 6
// speedup vs baseline: 1.1560x; 1.0585x over previous
#include <cuda_runtime.h>

// HaversineSmoothedLoss — split precompute + branchless fused main kernel.
//   a  = (1 - u1·u2)/2            (unit 3-vectors; no per-pair trig)
//   w  = exp2( sqrt(a) * Q(a) )   Q = K*log2(e) * asin-series; far cells underflow to 0
//   loss_b = log(Z_b) - (Σ w·x)/S_b ,  Z = Σ e^x, S = Σ w
//
// K0: celltab unit vectors, planar float arrays (computed once).
// K1: 2048 blocks (512 thr) = 128 row-groups (4 rows) × 16 chunks (2048 cells).
//     One float4 quad/thread, 4 rows. Branchless 15-inst/elem inner loop.
//     Celltab via L2 (__ldg, no SMEM staging — reuse is cross-block).
//     Last block (arrival counter) reduces partials to the loss.

#define C_CELLS 32768
#define B_ROWS  512
#define RPB     4
#define SPLIT   16
#define CHUNK   (C_CELLS / SPLIT)          // 2048
#define THREADS 512
#define NWARPS  (THREADS / 32)             // 16
#define GRID    ((B_ROWS / RPB) * SPLIT)   // 2048

__device__ float d_ux[C_CELLS];
__device__ float d_uy[C_CELLS];
__device__ float d_uz[C_CELLS];
__device__ float d_prow[3][B_ROWS];        // -0.5 * row unit vectors
__device__ float d_pZ[B_ROWS * SPLIT];
__device__ float d_pS[B_ROWS * SPLIT];
__device__ float d_pW[B_ROWS * SPLIT];
__device__ unsigned int d_ctr = 0;

__device__ __forceinline__ float fsqrt_ap(float a) {
    float r; asm("sqrt.approx.f32 %0, %1;" : "=f"(r) : "f"(a)); return r;
}
__device__ __forceinline__ float fexp2_ap(float a) {
    float r; asm("ex2.approx.f32 %0, %1;" : "=f"(r) : "f"(a)); return r;
}

__global__ void precompute(const float* __restrict__ geo,
                           const float* __restrict__ latlon) {
    const float d2r = 0.017453292519943295f;
    int i = blockIdx.x * blockDim.x + threadIdx.x;
    if (i < C_CELLS) {
        float lat = geo[2 * i]     * d2r;
        float lon = geo[2 * i + 1] * d2r;
        float sl, cl, so, co;
        sincosf(lat, &sl, &cl);
        sincosf(lon, &so, &co);
        d_ux[i] = sl;
        d_uy[i] = cl * so;
        d_uz[i] = cl * co;
    }
    if (i < B_ROWS) {
        float lat = latlon[2 * i]     * d2r;
        float lon = latlon[2 * i + 1] * d2r;
        float sl, cl, so, co;
        sincosf(lat, &sl, &cl);
        sincosf(lon, &so, &co);
        d_prow[0][i] = -0.5f * sl;
        d_prow[1][i] = -0.5f * cl * so;
        d_prow[2][i] = -0.5f * cl * co;
    }
}

__global__ __launch_bounds__(THREADS, 2)
void main_kernel(const float* __restrict__ logits,
                 float* __restrict__ out) {
    const int bx    = blockIdx.x;
    const int rg    = bx >> 4;             // row group 0..127
    const int ch    = bx & (SPLIT - 1);    // chunk 0..15
    const int row0  = rg * RPB;
    const int tid   = threadIdx.x;
    const int qidx  = (ch * CHUNK) / 4 + tid;   // this thread's float4 quad

    const float LOG2E = 1.4426950408889634f;
    const float KL  = -245.104328f;        // -(2*6371/75)*log2(e)
    const float KL3 = -40.8507213f;        // KL/6
    const float KL5 = -18.3828246f;        // KL*3/40
    const float KL7 = -10.9421575f;        // KL*15/336

    // Celltab quad (L2 resident after first wave).
    const float4 gx = __ldg((const float4*)d_ux + qidx);
    const float4 gy = __ldg((const float4*)d_uy + qidx);
    const float4 gz = __ldg((const float4*)d_uz + qidx);
    const float gxs[4] = {gx.x, gx.y, gx.z, gx.w};
    const float gys[4] = {gy.x, gy.y, gy.z, gy.w};
    const float gzs[4] = {gz.x, gz.y, gz.z, gz.w};

    // Front-batched logits loads (4 x LDG.128, independent).
    const float4* __restrict__ lg4 = (const float4*)logits;
    float4 xr[RPB];
    #pragma unroll
    for (int r = 0; r < RPB; r++)
        xr[r] = __ldg(lg4 + (size_t)(row0 + r) * (C_CELLS / 4) + qidx);

    float Z[RPB], S[RPB], WX[RPB];
    #pragma unroll
    for (int r = 0; r < RPB; r++) { Z[r] = 0.f; S[r] = 0.f; WX[r] = 0.f; }

    #pragma unroll
    for (int r = 0; r < RPB; r++) {
        const float nxr = d_prow[0][row0 + r];   // uniform across block -> LDCU/L2 hit
        const float nyr = d_prow[1][row0 + r];
        const float nzr = d_prow[2][row0 + r];
        const float xs[4] = {xr[r].x, xr[r].y, xr[r].z, xr[r].w};
        #pragma unroll
        for (int k = 0; k < 4; k++) {
            const float x = xs[k];
            Z[r] += fexp2_ap(x * LOG2E);
            float a = fmaf(nxr, gxs[k], fmaf(nyr, gys[k], fmaf(nzr, gzs[k], 0.5f)));
            a = fmaxf(a, 1e-18f);
            float s = fsqrt_ap(a);
            float q = fmaf(a, fmaf(a, fmaf(a, KL7, KL5), KL3), KL);
            float w = fexp2_ap(s * q);       // underflows to 0 for far cells
            S[r]  += w;
            WX[r]  = fmaf(w, x, WX[r]);
        }
    }

    // ---- Block reduction of 12 accumulators (deterministic tree) ----
    float acc[3 * RPB];
    #pragma unroll
    for (int r = 0; r < RPB; r++) {
        acc[r * 3 + 0] = Z[r]; acc[r * 3 + 1] = S[r]; acc[r * 3 + 2] = WX[r];
    }
    __shared__ float red[3 * RPB][NWARPS];
    const int lane = tid & 31, warp = tid >> 5;
    #pragma unroll
    for (int i = 0; i < 3 * RPB; i++) {
        float vv = acc[i];
        #pragma unroll
        for (int o = 16; o > 0; o >>= 1) vv += __shfl_down_sync(0xffffffffu, vv, o);
        if (lane == 0) red[i][warp] = vv;
    }
    __syncthreads();
    if (tid < 3 * RPB) {
        float vv = 0.f;
        #pragma unroll
        for (int wi = 0; wi < NWARPS; wi++) vv += red[tid][wi];
        const int r     = tid / 3;
        const int which = tid % 3;
        const int idx   = (row0 + r) * SPLIT + ch;
        if      (which == 0) d_pZ[idx] = vv;
        else if (which == 1) d_pS[idx] = vv;
        else                 d_pW[idx] = vv;
    }

    // ---- Last block reduces everything ----
    __shared__ bool isLast;
    __syncthreads();
    if (tid == 0) {
        __threadfence();
        unsigned int t = atomicAdd(&d_ctr, 1u);
        isLast = (t == (unsigned int)(GRID - 1));
    }
    __syncthreads();

    if (isLast) {
        const int b = tid;                  // 512 threads: one row each
        float Zt = 0.f, St = 0.f, Wt = 0.f;
        #pragma unroll
        for (int cc = 0; cc < SPLIT; cc++) {
            Zt += __ldcg(&d_pZ[b * SPLIT + cc]);
            St += __ldcg(&d_pS[b * SPLIT + cc]);
            Wt += __ldcg(&d_pW[b * SPLIT + cc]);
        }
        float vv = logf(Zt) - Wt * __fdividef(1.0f, St);

        __shared__ float fin[NWARPS];
        #pragma unroll
        for (int o = 16; o > 0; o >>= 1) vv += __shfl_down_sync(0xffffffffu, vv, o);
        if (lane == 0) fin[warp] = vv;
        __syncthreads();
        if (tid == 0) {
            float s = 0.f;
            #pragma unroll
            for (int i = 0; i < NWARPS; i++) s += fin[i];
            out[0] = s * (1.0f / (float)B_ROWS);
            d_ctr  = 0;   // reset for graph replay
        }
    }
}

extern "C" void kernel_launch(void* const* d_in, const int* in_sizes, int n_in,
                              void* d_out, int out_size) {
    const float* logits = (const float*)d_in[0];   // [512, 32768]
    const float* latlon = (const float*)d_in[1];   // [512, 2]
    const float* geo    = (const float*)d_in[2];   // [32768, 2]

    precompute<<<(C_CELLS + 255) / 256, 256>>>(geo, latlon);
    main_kernel<<<GRID, THREADS>>>(logits, (float*)d_out);
}

// round 7
// speedup vs baseline: 1.8290x; 1.5823x over previous
#include <cuda_runtime.h>

// HaversineSmoothedLoss — split precompute + amortized branchless main kernel.
//   a  = (1 - u1·u2)/2            (unit 3-vectors; no per-pair trig)
//   w  = exp2( sqrt(|a|) * Q(a) ) Q = K*log2(e) * asin-series; far cells underflow to 0
//   loss_b = log(Z_b) - (Σ w·x)/S_b ,  Z = Σ e^x, S = Σ w
//
// K0: celltab unit vectors (once).
// K1: 512 blocks (256 thr) = 128 row-groups (4 rows) × 4 chunks (8192 cells).
//     8 iterations/thread (1 float4 quad × 4 rows each) -> reduction overhead
//     amortized 8x vs round 6. Single wave at 4 blocks/SM.
//     Last block (arrival counter) reduces partials to the loss.

#define C_CELLS 32768
#define B_ROWS  512
#define RPB     4
#define SPLIT   4
#define CHUNK   (C_CELLS / SPLIT)          // 8192
#define THREADS 256
#define NWARPS  (THREADS / 32)             // 8
#define ITERS   (CHUNK / (4 * THREADS))    // 8
#define GRID    ((B_ROWS / RPB) * SPLIT)   // 512

__device__ float d_ux[C_CELLS];
__device__ float d_uy[C_CELLS];
__device__ float d_uz[C_CELLS];
__device__ float d_prow[3][B_ROWS];        // -0.5 * row unit vectors
__device__ float d_pZ[B_ROWS * SPLIT];
__device__ float d_pS[B_ROWS * SPLIT];
__device__ float d_pW[B_ROWS * SPLIT];
__device__ unsigned int d_ctr = 0;

__device__ __forceinline__ float fsqrt_ap(float a) {
    float r; asm("sqrt.approx.f32 %0, %1;" : "=f"(r) : "f"(a)); return r;
}
__device__ __forceinline__ float fexp2_ap(float a) {
    float r; asm("ex2.approx.f32 %0, %1;" : "=f"(r) : "f"(a)); return r;
}

__global__ void precompute(const float* __restrict__ geo,
                           const float* __restrict__ latlon) {
    const float d2r = 0.017453292519943295f;
    int i = blockIdx.x * blockDim.x + threadIdx.x;
    if (i < C_CELLS) {
        float lat = geo[2 * i]     * d2r;
        float lon = geo[2 * i + 1] * d2r;
        float sl, cl, so, co;
        sincosf(lat, &sl, &cl);
        sincosf(lon, &so, &co);
        d_ux[i] = sl;
        d_uy[i] = cl * so;
        d_uz[i] = cl * co;
    }
    if (i < B_ROWS) {
        float lat = latlon[2 * i]     * d2r;
        float lon = latlon[2 * i + 1] * d2r;
        float sl, cl, so, co;
        sincosf(lat, &sl, &cl);
        sincosf(lon, &so, &co);
        d_prow[0][i] = -0.5f * sl;
        d_prow[1][i] = -0.5f * cl * so;
        d_prow[2][i] = -0.5f * cl * co;
    }
}

__global__ __launch_bounds__(THREADS, 4)
void main_kernel(const float* __restrict__ logits,
                 float* __restrict__ out) {
    const int bx    = blockIdx.x;
    const int rg    = bx >> 2;             // row group 0..127
    const int ch    = bx & (SPLIT - 1);    // chunk 0..3
    const int row0  = rg * RPB;
    const int tid   = threadIdx.x;
    const int qbase = (ch * CHUNK) >> 2;   // float4 quad base of this chunk

    const float LOG2E = 1.4426950408889634f;
    const float KL  = -245.104328f;        // -(2*6371/75)*log2(e)
    const float KL3 = -40.8507213f;        // KL/6
    const float KL5 = -18.3828246f;        // KL*3/40
    const float KL7 = -10.9421575f;        // KL*15/336

    // Row uniforms (block-uniform loads).
    float nx[RPB], ny[RPB], nz[RPB];
    #pragma unroll
    for (int r = 0; r < RPB; r++) {
        nx[r] = d_prow[0][row0 + r];
        ny[r] = d_prow[1][row0 + r];
        nz[r] = d_prow[2][row0 + r];
    }

    const float4* __restrict__ lg4 = (const float4*)logits;
    const float4* __restrict__ ux4 = (const float4*)d_ux;
    const float4* __restrict__ uy4 = (const float4*)d_uy;
    const float4* __restrict__ uz4 = (const float4*)d_uz;

    float Z[RPB], S[RPB], WX[RPB];
    #pragma unroll
    for (int r = 0; r < RPB; r++) { Z[r] = 0.f; S[r] = 0.f; WX[r] = 0.f; }

    #pragma unroll 1
    for (int it = 0; it < ITERS; it++) {
        const int q = qbase + it * THREADS + tid;

        // Front-batch all 7 LDG.128 for this iteration.
        float4 xr[RPB];
        #pragma unroll
        for (int r = 0; r < RPB; r++)
            xr[r] = __ldg(lg4 + (size_t)(row0 + r) * (C_CELLS / 4) + q);
        const float4 gx = __ldg(ux4 + q);
        const float4 gy = __ldg(uy4 + q);
        const float4 gz = __ldg(uz4 + q);

        const float gxs[4] = {gx.x, gx.y, gx.z, gx.w};
        const float gys[4] = {gy.x, gy.y, gy.z, gy.w};
        const float gzs[4] = {gz.x, gz.y, gz.z, gz.w};

        #pragma unroll
        for (int r = 0; r < RPB; r++) {
            const float xs[4] = {xr[r].x, xr[r].y, xr[r].z, xr[r].w};
            #pragma unroll
            for (int k = 0; k < 4; k++) {
                const float x = xs[k];
                Z[r] += fexp2_ap(x * LOG2E);
                float a = fmaf(nx[r], gxs[k], fmaf(ny[r], gys[k], fmaf(nz[r], gzs[k], 0.5f)));
                float s = fsqrt_ap(fabsf(a));        // |a|: free operand modifier
                float qq = fmaf(a, fmaf(a, fmaf(a, KL7, KL5), KL3), KL);
                float w = fexp2_ap(s * qq);          // underflows to 0 for far cells
                S[r]  += w;
                WX[r]  = fmaf(w, x, WX[r]);
            }
        }
    }

    // ---- Block reduction of 12 accumulators (deterministic tree) ----
    float acc[3 * RPB];
    #pragma unroll
    for (int r = 0; r < RPB; r++) {
        acc[r * 3 + 0] = Z[r]; acc[r * 3 + 1] = S[r]; acc[r * 3 + 2] = WX[r];
    }
    __shared__ float red[3 * RPB][NWARPS];
    const int lane = tid & 31, warp = tid >> 5;
    #pragma unroll
    for (int i = 0; i < 3 * RPB; i++) {
        float vv = acc[i];
        #pragma unroll
        for (int o = 16; o > 0; o >>= 1) vv += __shfl_down_sync(0xffffffffu, vv, o);
        if (lane == 0) red[i][warp] = vv;
    }
    __syncthreads();
    if (tid < 3 * RPB) {
        float vv = 0.f;
        #pragma unroll
        for (int wi = 0; wi < NWARPS; wi++) vv += red[tid][wi];
        const int r     = tid / 3;
        const int which = tid % 3;
        const int idx   = (row0 + r) * SPLIT + ch;
        if      (which == 0) d_pZ[idx] = vv;
        else if (which == 1) d_pS[idx] = vv;
        else                 d_pW[idx] = vv;
    }

    // ---- Last block reduces everything ----
    __shared__ bool isLast;
    __syncthreads();
    if (tid == 0) {
        __threadfence();
        unsigned int t = atomicAdd(&d_ctr, 1u);
        isLast = (t == (unsigned int)(GRID - 1));
    }
    __syncthreads();

    if (isLast) {
        float v = 0.f;
        #pragma unroll
        for (int half = 0; half < B_ROWS / THREADS; half++) {   // 2 rows/thread
            const int b = tid + half * THREADS;
            float Zt = 0.f, St = 0.f, Wt = 0.f;
            #pragma unroll
            for (int cc = 0; cc < SPLIT; cc++) {
                Zt += __ldcg(&d_pZ[b * SPLIT + cc]);
                St += __ldcg(&d_pS[b * SPLIT + cc]);
                Wt += __ldcg(&d_pW[b * SPLIT + cc]);
            }
            v += logf(Zt) - Wt * __fdividef(1.0f, St);
        }
        __shared__ float fin[NWARPS];
        #pragma unroll
        for (int o = 16; o > 0; o >>= 1) v += __shfl_down_sync(0xffffffffu, v, o);
        if (lane == 0) fin[warp] = v;
        __syncthreads();
        if (tid == 0) {
            float s = 0.f;
            #pragma unroll
            for (int i = 0; i < NWARPS; i++) s += fin[i];
            out[0] = s * (1.0f / (float)B_ROWS);
            d_ctr  = 0;   // reset for graph replay
        }
    }
}

extern "C" void kernel_launch(void* const* d_in, const int* in_sizes, int n_in,
                              void* d_out, int out_size) {
    const float* logits = (const float*)d_in[0];   // [512, 32768]
    const float* latlon = (const float*)d_in[1];   // [512, 2]
    const float* geo    = (const float*)d_in[2];   // [32768, 2]

    precompute<<<(C_CELLS + 255) / 256, 256>>>(geo, latlon);
    main_kernel<<<GRID, THREADS>>>(logits, (float*)d_out);
}